// round 4
// baseline (speedup 1.0000x reference)
#include <cuda_runtime.h>
#include <cuda_bf16.h>
#include <cstddef>

// Problem constants (fixed shapes)
#define B_SZ 2
#define T_SZ 2048
#define C_SZ 1024
#define H_SZ 16
#define D_SZ 64
#define M_SZ (B_SZ * T_SZ)          // 4096 rows
#define QKV_N (3 * C_SZ)            // 3072

// Scratch (no cudaMalloc allowed)
__device__ float g_qkv[(size_t)M_SZ * QKV_N]; // 48 MB
__device__ float g_y[(size_t)M_SZ * C_SZ];    // 16 MB

// ---------------------------------------------------------------------------
// NT GEMM: C[M,N] = A[M,K] @ B[N,K]^T   (both operands K-contiguous row-major)
// 128x128 block tile, BK=8, 256 threads, 8x8 micro-tile per thread.
// ---------------------------------------------------------------------------
__global__ __launch_bounds__(256) void gemm_nt(const float* __restrict__ A,
                                               const float* __restrict__ B,
                                               float* __restrict__ C,
                                               int M, int N, int K) {
    __shared__ float As[8][132];
    __shared__ float Bs[8][132];

    const int tid = threadIdx.x;
    const int bm = blockIdx.y * 128;
    const int bn = blockIdx.x * 128;
    const int tx = tid & 15;
    const int ty = tid >> 4;

    const int lrow = tid >> 1;         // 0..127
    const int lcol = (tid & 1) * 4;    // 0 or 4

    const float* Aptr = A + (size_t)(bm + lrow) * K + lcol;
    const float* Bptr = B + (size_t)(bn + lrow) * K + lcol;

    float acc[8][8];
#pragma unroll
    for (int i = 0; i < 8; i++)
#pragma unroll
        for (int j = 0; j < 8; j++) acc[i][j] = 0.f;

    for (int k0 = 0; k0 < K; k0 += 8) {
        float4 a4 = *(const float4*)(Aptr + k0);
        float4 b4 = *(const float4*)(Bptr + k0);
        As[lcol + 0][lrow] = a4.x;
        As[lcol + 1][lrow] = a4.y;
        As[lcol + 2][lrow] = a4.z;
        As[lcol + 3][lrow] = a4.w;
        Bs[lcol + 0][lrow] = b4.x;
        Bs[lcol + 1][lrow] = b4.y;
        Bs[lcol + 2][lrow] = b4.z;
        Bs[lcol + 3][lrow] = b4.w;
        __syncthreads();

#pragma unroll
        for (int k = 0; k < 8; k++) {
            float a[8], b[8];
            *(float4*)&a[0] = *(const float4*)&As[k][ty * 8];
            *(float4*)&a[4] = *(const float4*)&As[k][ty * 8 + 4];
            *(float4*)&b[0] = *(const float4*)&Bs[k][tx * 8];
            *(float4*)&b[4] = *(const float4*)&Bs[k][tx * 8 + 4];
#pragma unroll
            for (int i = 0; i < 8; i++)
#pragma unroll
                for (int j = 0; j < 8; j++)
                    acc[i][j] = fmaf(a[i], b[j], acc[i][j]);
        }
        __syncthreads();
    }

#pragma unroll
    for (int i = 0; i < 8; i++) {
        float* Crow = C + (size_t)(bm + ty * 8 + i) * N + bn + tx * 8;
        float4 c0 = make_float4(acc[i][0], acc[i][1], acc[i][2], acc[i][3]);
        float4 c1 = make_float4(acc[i][4], acc[i][5], acc[i][6], acc[i][7]);
        *(float4*)Crow = c0;
        *(float4*)(Crow + 4) = c1;
    }
}

// ---------------------------------------------------------------------------
// Fused causal attention with additive position bias and *8 scaling.
// Block = (qt, h, b), 256 threads, 64 q-rows, streaming 64-key tiles,
// online (flash) softmax. logits = (q.k + bias) * 8, causal mask, softmax, P@V.
// ---------------------------------------------------------------------------
#define P68 68
#define SMEM_ATTN ((4 * 64 * P68 + 64 * 17 + 3 * 64) * 4)

__global__ __launch_bounds__(256) void attn_kernel(const float* __restrict__ qkv,
                                                   const float* __restrict__ pbias,
                                                   float* __restrict__ y) {
    extern __shared__ float sm[];
    float* Qs = sm;                    // [d][t] 64x68
    float* Ks = Qs + 64 * P68;         // [d][s]
    float* Vs = Ks + 64 * P68;         // [s][d]
    float* Ps = Vs + 64 * P68;         // bias phase: [t][s]; P phase: [s][t]
    float* red = Ps + 64 * P68;        // [64][17]
    float* m_s = red + 64 * 17;        // [64]
    float* l_s = m_s + 64;             // [64]
    float* al_s = l_s + 64;            // [64]

    const int qt = blockIdx.x;
    const int h = blockIdx.y;
    const int b = blockIdx.z;
    const int tid = threadIdx.x;
    const int tx = tid & 15;
    const int ty = tid >> 4;
    const int t0 = qt * 64;

    const int lr = tid >> 4;          // 0..15
    const int lc = (tid & 15) * 4;    // 0..60

    // Load Q transposed into Qs[d][t]
#pragma unroll
    for (int i = 0; i < 4; i++) {
        int t = lr + i * 16;
        const float* qp = qkv + ((size_t)(b * T_SZ + t0 + t)) * QKV_N + h * D_SZ + lc;
        float4 q4 = *(const float4*)qp;
        Qs[(lc + 0) * P68 + t] = q4.x;
        Qs[(lc + 1) * P68 + t] = q4.y;
        Qs[(lc + 2) * P68 + t] = q4.z;
        Qs[(lc + 3) * P68 + t] = q4.w;
    }
    if (tid < 64) { m_s[tid] = -1e30f; l_s[tid] = 0.f; }

    float acc[4][4];
#pragma unroll
    for (int i = 0; i < 4; i++)
#pragma unroll
        for (int j = 0; j < 4; j++) acc[i][j] = 0.f;

    for (int kt = 0; kt <= qt; kt++) {
        const int s0 = kt * 64;
        __syncthreads();  // prior PV done (and Q/stat init visible on iter 0)

        // Load K (transposed), V (direct), bias tile (into Ps as [t][s])
#pragma unroll
        for (int i = 0; i < 4; i++) {
            int s = lr + i * 16;
            size_t base = ((size_t)(b * T_SZ + s0 + s)) * QKV_N + h * D_SZ + lc;
            float4 k4 = *(const float4*)(qkv + C_SZ + base);
            Ks[(lc + 0) * P68 + s] = k4.x;
            Ks[(lc + 1) * P68 + s] = k4.y;
            Ks[(lc + 2) * P68 + s] = k4.z;
            Ks[(lc + 3) * P68 + s] = k4.w;
            float4 v4 = *(const float4*)(qkv + 2 * C_SZ + base);
            *(float4*)&Vs[s * P68 + lc] = v4;
            int t = lr + i * 16;
            float4 bb = *(const float4*)(pbias + ((size_t)h * T_SZ + t0 + t) * T_SZ + s0 + lc);
            *(float4*)&Ps[t * P68 + lc] = bb;
        }
        __syncthreads();

        // S = Q K^T (4x4 per thread), + bias, *8, causal mask
        float sreg[4][4];
#pragma unroll
        for (int i = 0; i < 4; i++)
#pragma unroll
            for (int j = 0; j < 4; j++) sreg[i][j] = 0.f;

#pragma unroll 4
        for (int d = 0; d < 64; d++) {
            float4 qa = *(const float4*)&Qs[d * P68 + ty * 4];
            float4 kb = *(const float4*)&Ks[d * P68 + tx * 4];
            float qv[4] = {qa.x, qa.y, qa.z, qa.w};
            float kv[4] = {kb.x, kb.y, kb.z, kb.w};
#pragma unroll
            for (int i = 0; i < 4; i++)
#pragma unroll
                for (int j = 0; j < 4; j++)
                    sreg[i][j] = fmaf(qv[i], kv[j], sreg[i][j]);
        }
#pragma unroll
        for (int i = 0; i < 4; i++) {
            int t = ty * 4 + i;
#pragma unroll
            for (int j = 0; j < 4; j++) {
                int s = tx * 4 + j;
                float v = (sreg[i][j] + Ps[t * P68 + s]) * 8.0f;
                if (s0 + s > t0 + t) v = -1e30f;
                sreg[i][j] = v;
            }
        }
        __syncthreads();  // bias reads done; Ps reusable; red reusable

        // Row max (partial over this thread's 4 cols), reduce across tx
#pragma unroll
        for (int i = 0; i < 4; i++) {
            float pm = sreg[i][0];
            pm = fmaxf(pm, sreg[i][1]);
            pm = fmaxf(pm, sreg[i][2]);
            pm = fmaxf(pm, sreg[i][3]);
            red[(ty * 4 + i) * 17 + tx] = pm;
        }
        __syncthreads();
        if (tid < 64) {
            float m_old = m_s[tid];
            float mx = m_old;
#pragma unroll
            for (int c = 0; c < 16; c++) mx = fmaxf(mx, red[tid * 17 + c]);
            float al = __expf(m_old - mx);
            m_s[tid] = mx;
            al_s[tid] = al;
            l_s[tid] *= al;
        }
        __syncthreads();

        // Rescale acc, exponentiate, write P (as [s][t]), partial row sums
#pragma unroll
        for (int i = 0; i < 4; i++) {
            float al = al_s[ty * 4 + i];
#pragma unroll
            for (int j = 0; j < 4; j++) acc[i][j] *= al;
        }
#pragma unroll
        for (int i = 0; i < 4; i++) {
            float m = m_s[ty * 4 + i];
            float prow = 0.f;
#pragma unroll
            for (int j = 0; j < 4; j++) {
                float p = __expf(sreg[i][j] - m);
                prow += p;
                Ps[(tx * 4 + j) * P68 + ty * 4 + i] = p;
            }
            red[(ty * 4 + i) * 17 + tx] = prow;
        }
        __syncthreads();
        if (tid < 64) {
            float s = 0.f;
#pragma unroll
            for (int c = 0; c < 16; c++) s += red[tid * 17 + c];
            l_s[tid] += s;
        }

        // PV: acc[t][d] += sum_k P[k][t] * V[k][d]
#pragma unroll 4
        for (int kk = 0; kk < 64; kk++) {
            float4 pa = *(const float4*)&Ps[kk * P68 + ty * 4];
            float4 vb = *(const float4*)&Vs[kk * P68 + tx * 4];
            float pv[4] = {pa.x, pa.y, pa.z, pa.w};
            float vv[4] = {vb.x, vb.y, vb.z, vb.w};
#pragma unroll
            for (int i = 0; i < 4; i++)
#pragma unroll
                for (int j = 0; j < 4; j++)
                    acc[i][j] = fmaf(pv[i], vv[j], acc[i][j]);
        }
    }

    __syncthreads();  // l_s final
#pragma unroll
    for (int i = 0; i < 4; i++) {
        int t = t0 + ty * 4 + i;
        float inv = 1.0f / l_s[ty * 4 + i];
        float4 o = make_float4(acc[i][0] * inv, acc[i][1] * inv,
                               acc[i][2] * inv, acc[i][3] * inv);
        *(float4*)(y + ((size_t)(b * T_SZ + t)) * C_SZ + h * D_SZ + tx * 4) = o;
    }
}

// ---------------------------------------------------------------------------
extern "C" void kernel_launch(void* const* d_in, const int* in_sizes, int n_in,
                              void* d_out, int out_size) {
    const float* x      = (const float*)d_in[0];
    const float* pbias  = (const float*)d_in[1];
    const float* W_attn = (const float*)d_in[2];
    const float* W_proj = (const float*)d_in[3];
    float* out = (float*)d_out;

    float* qkv = nullptr;
    float* y = nullptr;
    cudaGetSymbolAddress((void**)&qkv, g_qkv);
    cudaGetSymbolAddress((void**)&y, g_y);

    cudaFuncSetAttribute(attn_kernel, cudaFuncAttributeMaxDynamicSharedMemorySize,
                         SMEM_ATTN);

    // 1) qkv = x @ W_attn^T   [4096,1024] x [3072,1024]^T
    {
        dim3 grid(QKV_N / 128, M_SZ / 128);
        gemm_nt<<<grid, 256>>>(x, W_attn, qkv, M_SZ, QKV_N, C_SZ);
    }
    // 2) fused causal attention
    {
        dim3 grid(T_SZ / 64, H_SZ, B_SZ);
        attn_kernel<<<grid, 256, SMEM_ATTN>>>(qkv, pbias, y);
    }
    // 3) out = y @ W_proj^T   [4096,1024] x [1024,1024]^T
    {
        dim3 grid(C_SZ / 128, M_SZ / 128);
        gemm_nt<<<grid, 256>>>(y, W_proj, out, M_SZ, C_SZ, C_SZ);
    }
}

// round 6
// speedup vs baseline: 1.3873x; 1.3873x over previous
#include <cuda_runtime.h>
#include <cuda_bf16.h>
#include <cstdint>
#include <cstddef>

// Problem constants (fixed shapes)
#define B_SZ 2
#define T_SZ 2048
#define C_SZ 1024
#define H_SZ 16
#define D_SZ 64
#define M_SZ (B_SZ * T_SZ)          // 4096 rows
#define QKV_N (3 * C_SZ)            // 3072
#define KP    (3 * C_SZ)            // split K' = 3072

// Scratch (no cudaMalloc allowed)
__device__ float g_qkv[(size_t)M_SZ * QKV_N];                 // 48 MB fp32
__device__ float g_y[(size_t)M_SZ * C_SZ];                    // 16 MB fp32
__device__ __nv_bfloat16 g_xs [(size_t)M_SZ * KP];            // x split  [4096,3072]
__device__ __nv_bfloat16 g_was[(size_t)QKV_N * KP];           // W_attn split [3072,3072]
__device__ __nv_bfloat16 g_wps[(size_t)C_SZ * KP];            // W_proj split [1024,3072]
__device__ __nv_bfloat16 g_ys [(size_t)M_SZ * KP];            // y split  [4096,3072]

// ---------------------------------------------------------------------------
// PTX helpers
// ---------------------------------------------------------------------------
__device__ __forceinline__ uint32_t smem_u32(const void* p) {
    uint32_t a;
    asm("{ .reg .u64 t; cvta.to.shared.u64 t, %1; cvt.u32.u64 %0, t; }"
        : "=r"(a) : "l"(p));
    return a;
}

__device__ __forceinline__ void cp_async16(uint32_t saddr, const void* gaddr) {
    asm volatile("cp.async.cg.shared.global [%0], [%1], 16;"
                 :: "r"(saddr), "l"(gaddr));
}
__device__ __forceinline__ void cp_commit() {
    asm volatile("cp.async.commit_group;");
}
template <int N>
__device__ __forceinline__ void cp_wait() {
    asm volatile("cp.async.wait_group %0;" :: "n"(N));
}

__device__ __forceinline__ void ldm_x4(uint32_t addr, uint32_t& r0, uint32_t& r1,
                                       uint32_t& r2, uint32_t& r3) {
    asm volatile("ldmatrix.sync.aligned.m8n8.x4.shared.b16 {%0,%1,%2,%3}, [%4];"
                 : "=r"(r0), "=r"(r1), "=r"(r2), "=r"(r3) : "r"(addr));
}

__device__ __forceinline__ void mma_16816(float* c, const uint32_t* a,
                                          uint32_t b0, uint32_t b1) {
    asm volatile("mma.sync.aligned.m16n8k16.row.col.f32.bf16.bf16.f32 "
                 "{%0,%1,%2,%3}, {%4,%5,%6,%7}, {%8,%9}, {%0,%1,%2,%3};"
                 : "+f"(c[0]), "+f"(c[1]), "+f"(c[2]), "+f"(c[3])
                 : "r"(a[0]), "r"(a[1]), "r"(a[2]), "r"(a[3]),
                   "r"(b0), "r"(b1));
}

// ---------------------------------------------------------------------------
// Split-precision conversion: fp32 [rows,1024] -> bf16 [rows,3072]
// mode 0 (A side): [hi | lo | hi] ; mode 1 (B side): [hi | hi | lo]
// ---------------------------------------------------------------------------
__global__ __launch_bounds__(256) void split_bf16(const float* __restrict__ in,
                                                  __nv_bfloat16* __restrict__ out,
                                                  int rows, int mode) {
    size_t i = (size_t)blockIdx.x * 256 + threadIdx.x; // pair index
    size_t total = (size_t)rows * 512;
    if (i >= total) return;
    size_t r = i >> 9;
    int c = (int)(i & 511) * 2;
    float2 v = *(const float2*)(in + r * 1024 + c);
    __nv_bfloat16 h0 = __float2bfloat16_rn(v.x);
    __nv_bfloat16 h1 = __float2bfloat16_rn(v.y);
    __nv_bfloat16 l0 = __float2bfloat16_rn(v.x - __bfloat162float(h0));
    __nv_bfloat16 l1 = __float2bfloat16_rn(v.y - __bfloat162float(h1));
    __nv_bfloat162 H; H.x = h0; H.y = h1;
    __nv_bfloat162 L; L.x = l0; L.y = l1;
    __nv_bfloat16* o = out + r * 3072 + c;
    if (mode == 0) {
        *(__nv_bfloat162*)(o)        = H;
        *(__nv_bfloat162*)(o + 1024) = L;
        *(__nv_bfloat162*)(o + 2048) = H;
    } else {
        *(__nv_bfloat162*)(o)        = H;
        *(__nv_bfloat162*)(o + 1024) = H;
        *(__nv_bfloat162*)(o + 2048) = L;
    }
}

// ---------------------------------------------------------------------------
// HMMA bf16 GEMM:  C[M,N] = A[M,Kp] @ B[N,Kp]^T  (fp32 out)
// 128x128 CTA tile, BK=32, 256 threads (8 warps, 32x64 each), cp.async
// double buffering. smem rows padded to 80B (conflict-free ldmatrix).
// ---------------------------------------------------------------------------
#define BKQ 32
#define ROWB 80                      // bytes per smem row (32*2 + 16 pad)
#define TILE_BYTES (128 * ROWB)      // 10240 per operand per buffer

__global__ __launch_bounds__(256) void gemm_mma(const __nv_bfloat16* __restrict__ A,
                                                const __nv_bfloat16* __restrict__ B,
                                                float* __restrict__ C,
                                                int M, int N, int Kp) {
    __shared__ __align__(16) char smem[4 * TILE_BYTES]; // A0,A1,B0,B1

    const int tid = threadIdx.x;
    const int wid = tid >> 5;
    const int lane = tid & 31;
    const int bm = blockIdx.y * 128;
    const int bn = blockIdx.x * 128;

    const uint32_t sbase = smem_u32(smem);
    const uint32_t sA0 = sbase;
    const uint32_t sB0 = sbase + 2 * TILE_BYTES;

    // load mapping: 2 chunks of 16B per thread per operand
    const int lr0 = tid >> 2;            // rows 0..63
    const int lcb = (tid & 3) * 16;      // byte col within 64B of data
    const int lce = (tid & 3) * 8;       // elem col

    const __nv_bfloat16* Abase = A + (size_t)(bm + lr0) * Kp + lce;
    const __nv_bfloat16* Bbase = B + (size_t)(bn + lr0) * Kp + lce;

    // ldmatrix addressing
    const int wm = wid & 3;              // 0..3 (M groups of 32)
    const int wn = wid >> 2;             // 0..1 (N groups of 64)
    const uint32_t lmr = lane & 15;
    const uint32_t lmc = (lane >> 4) * 16;

    float acc[2][8][4];
#pragma unroll
    for (int mt = 0; mt < 2; mt++)
#pragma unroll
        for (int nt = 0; nt < 8; nt++)
#pragma unroll
            for (int q = 0; q < 4; q++) acc[mt][nt][q] = 0.f;

    const int iters = Kp / BKQ;

    // prologue: load tile 0
    {
        uint32_t dA = sA0 + lr0 * ROWB + lcb;
        uint32_t dB = sB0 + lr0 * ROWB + lcb;
        cp_async16(dA, Abase);
        cp_async16(dA + 64 * ROWB, Abase + (size_t)64 * Kp);
        cp_async16(dB, Bbase);
        cp_async16(dB + 64 * ROWB, Bbase + (size_t)64 * Kp);
        cp_commit();
    }

    for (int i = 0; i < iters; i++) {
        const int buf = i & 1;
        if (i + 1 < iters) {
            const int nb = buf ^ 1;
            const int k0 = (i + 1) * BKQ;
            uint32_t dA = sA0 + nb * TILE_BYTES + lr0 * ROWB + lcb;
            uint32_t dB = sB0 + nb * TILE_BYTES + lr0 * ROWB + lcb;
            cp_async16(dA, Abase + k0);
            cp_async16(dA + 64 * ROWB, Abase + (size_t)64 * Kp + k0);
            cp_async16(dB, Bbase + k0);
            cp_async16(dB + 64 * ROWB, Bbase + (size_t)64 * Kp + k0);
            cp_commit();
            cp_wait<1>();
        } else {
            cp_wait<0>();
        }
        __syncthreads();

        const uint32_t aTile = sA0 + buf * TILE_BYTES;
        const uint32_t bTile = sB0 + buf * TILE_BYTES;

#pragma unroll
        for (int ks = 0; ks < 2; ks++) {
            uint32_t af[2][4];
#pragma unroll
            for (int mt = 0; mt < 2; mt++) {
                uint32_t addr = aTile + (wm * 32 + mt * 16 + lmr) * ROWB +
                                ks * 32 + lmc;
                ldm_x4(addr, af[mt][0], af[mt][1], af[mt][2], af[mt][3]);
            }
            uint32_t bf[4][4];
#pragma unroll
            for (int bt = 0; bt < 4; bt++) {
                uint32_t addr = bTile + (wn * 64 + bt * 16 + lmr) * ROWB +
                                ks * 32 + lmc;
                ldm_x4(addr, bf[bt][0], bf[bt][1], bf[bt][2], bf[bt][3]);
            }
#pragma unroll
            for (int mt = 0; mt < 2; mt++)
#pragma unroll
                for (int nt = 0; nt < 8; nt++) {
                    uint32_t b0 = bf[nt >> 1][nt & 1];
                    uint32_t b1 = bf[nt >> 1][(nt & 1) + 2];
                    mma_16816(acc[mt][nt], af[mt], b0, b1);
                }
        }
        __syncthreads();
    }

    // epilogue
    const int cr = lane >> 2;
    const int cc = (lane & 3) * 2;
#pragma unroll
    for (int mt = 0; mt < 2; mt++) {
        int r0 = bm + wm * 32 + mt * 16 + cr;
#pragma unroll
        for (int nt = 0; nt < 8; nt++) {
            int col = bn + wn * 64 + nt * 8 + cc;
            float2 v0 = make_float2(acc[mt][nt][0], acc[mt][nt][1]);
            float2 v1 = make_float2(acc[mt][nt][2], acc[mt][nt][3]);
            *(float2*)(C + (size_t)r0 * N + col) = v0;
            *(float2*)(C + (size_t)(r0 + 8) * N + col) = v1;
        }
    }
}

// ---------------------------------------------------------------------------
// Fused causal attention with additive position bias and *8 scaling (fp32).
// ---------------------------------------------------------------------------
#define P68 68
#define SMEM_ATTN ((4 * 64 * P68 + 64 * 17 + 3 * 64) * 4)

__global__ __launch_bounds__(256) void attn_kernel(const float* __restrict__ qkv,
                                                   const float* __restrict__ pbias,
                                                   float* __restrict__ y) {
    extern __shared__ float sm[];
    float* Qs = sm;                    // [d][t] 64x68
    float* Ks = Qs + 64 * P68;         // [d][s]
    float* Vs = Ks + 64 * P68;         // [s][d]
    float* Ps = Vs + 64 * P68;         // bias phase: [t][s]; P phase: [s][t]
    float* red = Ps + 64 * P68;        // [64][17]
    float* m_s = red + 64 * 17;        // [64]
    float* l_s = m_s + 64;             // [64]
    float* al_s = l_s + 64;            // [64]

    const int qt = blockIdx.x;
    const int h = blockIdx.y;
    const int b = blockIdx.z;
    const int tid = threadIdx.x;
    const int tx = tid & 15;
    const int ty = tid >> 4;
    const int t0 = qt * 64;

    const int lr = tid >> 4;          // 0..15
    const int lc = (tid & 15) * 4;    // 0..60

    // Load Q transposed into Qs[d][t]
#pragma unroll
    for (int i = 0; i < 4; i++) {
        int t = lr + i * 16;
        const float* qp = qkv + ((size_t)(b * T_SZ + t0 + t)) * QKV_N + h * D_SZ + lc;
        float4 q4 = *(const float4*)qp;
        Qs[(lc + 0) * P68 + t] = q4.x;
        Qs[(lc + 1) * P68 + t] = q4.y;
        Qs[(lc + 2) * P68 + t] = q4.z;
        Qs[(lc + 3) * P68 + t] = q4.w;
    }
    if (tid < 64) { m_s[tid] = -1e30f; l_s[tid] = 0.f; }

    float acc[4][4];
#pragma unroll
    for (int i = 0; i < 4; i++)
#pragma unroll
        for (int j = 0; j < 4; j++) acc[i][j] = 0.f;

    for (int kt = 0; kt <= qt; kt++) {
        const int s0 = kt * 64;
        __syncthreads();  // prior PV done (and Q/stat init visible on iter 0)

        // Load K (transposed), V (direct), bias tile (into Ps as [t][s])
#pragma unroll
        for (int i = 0; i < 4; i++) {
            int s = lr + i * 16;
            size_t base = ((size_t)(b * T_SZ + s0 + s)) * QKV_N + h * D_SZ + lc;
            float4 k4 = *(const float4*)(qkv + C_SZ + base);
            Ks[(lc + 0) * P68 + s] = k4.x;
            Ks[(lc + 1) * P68 + s] = k4.y;
            Ks[(lc + 2) * P68 + s] = k4.z;
            Ks[(lc + 3) * P68 + s] = k4.w;
            float4 v4 = *(const float4*)(qkv + 2 * C_SZ + base);
            *(float4*)&Vs[s * P68 + lc] = v4;
            int t = lr + i * 16;
            float4 bb = *(const float4*)(pbias + ((size_t)h * T_SZ + t0 + t) * T_SZ + s0 + lc);
            *(float4*)&Ps[t * P68 + lc] = bb;
        }
        __syncthreads();

        // S = Q K^T (4x4 per thread), + bias, *8, causal mask
        float sreg[4][4];
#pragma unroll
        for (int i = 0; i < 4; i++)
#pragma unroll
            for (int j = 0; j < 4; j++) sreg[i][j] = 0.f;

#pragma unroll 4
        for (int d = 0; d < 64; d++) {
            float4 qa = *(const float4*)&Qs[d * P68 + ty * 4];
            float4 kb = *(const float4*)&Ks[d * P68 + tx * 4];
            float qv[4] = {qa.x, qa.y, qa.z, qa.w};
            float kv[4] = {kb.x, kb.y, kb.z, kb.w};
#pragma unroll
            for (int i = 0; i < 4; i++)
#pragma unroll
                for (int j = 0; j < 4; j++)
                    sreg[i][j] = fmaf(qv[i], kv[j], sreg[i][j]);
        }
#pragma unroll
        for (int i = 0; i < 4; i++) {
            int t = ty * 4 + i;
#pragma unroll
            for (int j = 0; j < 4; j++) {
                int s = tx * 4 + j;
                float v = (sreg[i][j] + Ps[t * P68 + s]) * 8.0f;
                if (s0 + s > t0 + t) v = -1e30f;
                sreg[i][j] = v;
            }
        }
        __syncthreads();  // bias reads done; Ps reusable; red reusable

        // Row max (partial over this thread's 4 cols), reduce across tx
#pragma unroll
        for (int i = 0; i < 4; i++) {
            float pm = sreg[i][0];
            pm = fmaxf(pm, sreg[i][1]);
            pm = fmaxf(pm, sreg[i][2]);
            pm = fmaxf(pm, sreg[i][3]);
            red[(ty * 4 + i) * 17 + tx] = pm;
        }
        __syncthreads();
        if (tid < 64) {
            float m_old = m_s[tid];
            float mx = m_old;
#pragma unroll
            for (int c = 0; c < 16; c++) mx = fmaxf(mx, red[tid * 17 + c]);
            float al = __expf(m_old - mx);
            m_s[tid] = mx;
            al_s[tid] = al;
            l_s[tid] *= al;
        }
        __syncthreads();

        // Rescale acc, exponentiate, write P (as [s][t]), partial row sums
#pragma unroll
        for (int i = 0; i < 4; i++) {
            float al = al_s[ty * 4 + i];
#pragma unroll
            for (int j = 0; j < 4; j++) acc[i][j] *= al;
        }
#pragma unroll
        for (int i = 0; i < 4; i++) {
            float m = m_s[ty * 4 + i];
            float prow = 0.f;
#pragma unroll
            for (int j = 0; j < 4; j++) {
                float p = __expf(sreg[i][j] - m);
                prow += p;
                Ps[(tx * 4 + j) * P68 + ty * 4 + i] = p;
            }
            red[(ty * 4 + i) * 17 + tx] = prow;
        }
        __syncthreads();
        if (tid < 64) {
            float s = 0.f;
#pragma unroll
            for (int c = 0; c < 16; c++) s += red[tid * 17 + c];
            l_s[tid] += s;
        }

        // PV: acc[t][d] += sum_k P[k][t] * V[k][d]
#pragma unroll 4
        for (int kk = 0; kk < 64; kk++) {
            float4 pa = *(const float4*)&Ps[kk * P68 + ty * 4];
            float4 vb = *(const float4*)&Vs[kk * P68 + tx * 4];
            float pv[4] = {pa.x, pa.y, pa.z, pa.w};
            float vv[4] = {vb.x, vb.y, vb.z, vb.w};
#pragma unroll
            for (int i = 0; i < 4; i++)
#pragma unroll
                for (int j = 0; j < 4; j++)
                    acc[i][j] = fmaf(pv[i], vv[j], acc[i][j]);
        }
    }

    __syncthreads();  // l_s final
#pragma unroll
    for (int i = 0; i < 4; i++) {
        int t = t0 + ty * 4 + i;
        float inv = 1.0f / l_s[ty * 4 + i];
        float4 o = make_float4(acc[i][0] * inv, acc[i][1] * inv,
                               acc[i][2] * inv, acc[i][3] * inv);
        *(float4*)(y + ((size_t)(b * T_SZ + t)) * C_SZ + h * D_SZ + tx * 4) = o;
    }
}

// ---------------------------------------------------------------------------
extern "C" void kernel_launch(void* const* d_in, const int* in_sizes, int n_in,
                              void* d_out, int out_size) {
    const float* x      = (const float*)d_in[0];
    const float* pbias  = (const float*)d_in[1];
    const float* W_attn = (const float*)d_in[2];
    const float* W_proj = (const float*)d_in[3];
    float* out = (float*)d_out;

    float* qkv = nullptr;
    float* y = nullptr;
    __nv_bfloat16 *xs = nullptr, *was = nullptr, *wps = nullptr, *ys = nullptr;
    cudaGetSymbolAddress((void**)&qkv, g_qkv);
    cudaGetSymbolAddress((void**)&y, g_y);
    cudaGetSymbolAddress((void**)&xs, g_xs);
    cudaGetSymbolAddress((void**)&was, g_was);
    cudaGetSymbolAddress((void**)&wps, g_wps);
    cudaGetSymbolAddress((void**)&ys, g_ys);

    cudaFuncSetAttribute(attn_kernel, cudaFuncAttributeMaxDynamicSharedMemorySize,
                         SMEM_ATTN);

    // Split inputs to bf16 hi/lo concatenated along K
    split_bf16<<<(M_SZ * 512 + 255) / 256, 256>>>(x, xs, M_SZ, 0);
    split_bf16<<<(QKV_N * 512 + 255) / 256, 256>>>(W_attn, was, QKV_N, 1);
    split_bf16<<<(C_SZ * 512 + 255) / 256, 256>>>(W_proj, wps, C_SZ, 1);

    // 1) qkv = x @ W_attn^T via HMMA (K' = 3072)
    {
        dim3 grid(QKV_N / 128, M_SZ / 128);
        gemm_mma<<<grid, 256>>>(xs, was, qkv, M_SZ, QKV_N, KP);
    }
    // 2) fused causal attention (fp32)
    {
        dim3 grid(T_SZ / 64, H_SZ, B_SZ);
        attn_kernel<<<grid, 256, SMEM_ATTN>>>(qkv, pbias, y);
    }
    // 3) out = y @ W_proj^T via HMMA
    split_bf16<<<(M_SZ * 512 + 255) / 256, 256>>>(y, ys, M_SZ, 0);
    {
        dim3 grid(C_SZ / 128, M_SZ / 128);
        gemm_mma<<<grid, 256>>>(ys, wps, out, M_SZ, C_SZ, KP);
    }
}

// round 8
// speedup vs baseline: 2.3927x; 1.7247x over previous
#include <cuda_runtime.h>
#include <cuda_bf16.h>
#include <cstdint>
#include <cstddef>

// Problem constants (fixed shapes)
#define B_SZ 2
#define T_SZ 2048
#define C_SZ 1024
#define H_SZ 16
#define D_SZ 64
#define M_SZ (B_SZ * T_SZ)          // 4096 rows
#define QKV_N (3 * C_SZ)            // 3072
#define KP    (3 * C_SZ)            // split K' = 3072

// Scratch (no cudaMalloc allowed)
__device__ float g_qkv[(size_t)M_SZ * QKV_N];                 // 48 MB fp32
__device__ __nv_bfloat16 g_xs [(size_t)M_SZ * KP];            // x split  [4096,3072]
__device__ __nv_bfloat16 g_was[(size_t)QKV_N * KP];           // W_attn split [3072,3072]
__device__ __nv_bfloat16 g_wps[(size_t)C_SZ * KP];            // W_proj split [1024,3072]
__device__ __nv_bfloat16 g_ys [(size_t)M_SZ * KP];            // y split  [4096,3072]

// ---------------------------------------------------------------------------
// PTX helpers
// ---------------------------------------------------------------------------
__device__ __forceinline__ uint32_t smem_u32(const void* p) {
    uint32_t a;
    asm("{ .reg .u64 t; cvta.to.shared.u64 t, %1; cvt.u32.u64 %0, t; }"
        : "=r"(a) : "l"(p));
    return a;
}

__device__ __forceinline__ void cp_async16(uint32_t saddr, const void* gaddr) {
    asm volatile("cp.async.cg.shared.global [%0], [%1], 16;"
                 :: "r"(saddr), "l"(gaddr));
}
__device__ __forceinline__ void cp_commit() {
    asm volatile("cp.async.commit_group;");
}
template <int N>
__device__ __forceinline__ void cp_wait() {
    asm volatile("cp.async.wait_group %0;" :: "n"(N));
}

__device__ __forceinline__ void ldm_x4(uint32_t addr, uint32_t& r0, uint32_t& r1,
                                       uint32_t& r2, uint32_t& r3) {
    asm volatile("ldmatrix.sync.aligned.m8n8.x4.shared.b16 {%0,%1,%2,%3}, [%4];"
                 : "=r"(r0), "=r"(r1), "=r"(r2), "=r"(r3) : "r"(addr));
}

__device__ __forceinline__ void ldm_x4_t(uint32_t addr, uint32_t& r0, uint32_t& r1,
                                         uint32_t& r2, uint32_t& r3) {
    asm volatile("ldmatrix.sync.aligned.m8n8.x4.trans.shared.b16 {%0,%1,%2,%3}, [%4];"
                 : "=r"(r0), "=r"(r1), "=r"(r2), "=r"(r3) : "r"(addr));
}

__device__ __forceinline__ void mma_16816(float* c, const uint32_t* a,
                                          uint32_t b0, uint32_t b1) {
    asm volatile("mma.sync.aligned.m16n8k16.row.col.f32.bf16.bf16.f32 "
                 "{%0,%1,%2,%3}, {%4,%5,%6,%7}, {%8,%9}, {%0,%1,%2,%3};"
                 : "+f"(c[0]), "+f"(c[1]), "+f"(c[2]), "+f"(c[3])
                 : "r"(a[0]), "r"(a[1]), "r"(a[2]), "r"(a[3]),
                   "r"(b0), "r"(b1));
}

// pack bf16-truncations of (a=low half, b=high half) into one u32
__device__ __forceinline__ uint32_t prmt_hi(float a, float b) {
    uint32_t r;
    asm("prmt.b32 %0, %1, %2, 0x7632;"
        : "=r"(r) : "r"(__float_as_uint(a)), "r"(__float_as_uint(b)));
    return r;
}
// rounded pack: lo in low half, hi in high half
__device__ __forceinline__ uint32_t cvt_bf2(float lo, float hi) {
    uint32_t r;
    asm("cvt.rn.bf16x2.f32 %0, %1, %2;" : "=r"(r) : "f"(hi), "f"(lo));
    return r;
}
__device__ __forceinline__ float ftrunc_bf(float x) {
    return __uint_as_float(__float_as_uint(x) & 0xffff0000u);
}
__device__ __forceinline__ float qmax(float v) {
    v = fmaxf(v, __shfl_xor_sync(0xffffffffu, v, 1));
    v = fmaxf(v, __shfl_xor_sync(0xffffffffu, v, 2));
    return v;
}
__device__ __forceinline__ float qsum(float v) {
    v += __shfl_xor_sync(0xffffffffu, v, 1);
    v += __shfl_xor_sync(0xffffffffu, v, 2);
    return v;
}

// ---------------------------------------------------------------------------
// Split-precision conversion: fp32 [rows,1024] -> bf16 [rows,3072]
// mode 0 (A side): [hi | lo | hi] ; mode 1 (B side): [hi | hi | lo]
// ---------------------------------------------------------------------------
__global__ __launch_bounds__(256) void split_bf16(const float* __restrict__ in,
                                                  __nv_bfloat16* __restrict__ out,
                                                  int rows, int mode) {
    size_t i = (size_t)blockIdx.x * 256 + threadIdx.x; // pair index
    size_t total = (size_t)rows * 512;
    if (i >= total) return;
    size_t r = i >> 9;
    int c = (int)(i & 511) * 2;
    float2 v = *(const float2*)(in + r * 1024 + c);
    uint32_t H = prmt_hi(v.x, v.y);
    uint32_t L = cvt_bf2(v.x - ftrunc_bf(v.x), v.y - ftrunc_bf(v.y));
    uint32_t* o = (uint32_t*)(out + r * 3072 + c);
    if (mode == 0) {
        o[0] = H; o[512] = L; o[1024] = H;
    } else {
        o[0] = H; o[512] = H; o[1024] = L;
    }
}

// ---------------------------------------------------------------------------
// HMMA bf16 GEMM:  C[M,N] = A[M,Kp] @ B[N,Kp]^T  (fp32 out)
// ---------------------------------------------------------------------------
#define BKQ 32
#define ROWB 80
#define TILE_BYTES (128 * ROWB)

__global__ __launch_bounds__(256) void gemm_mma(const __nv_bfloat16* __restrict__ A,
                                                const __nv_bfloat16* __restrict__ B,
                                                float* __restrict__ C,
                                                int M, int N, int Kp) {
    __shared__ __align__(16) char smem[4 * TILE_BYTES];

    const int tid = threadIdx.x;
    const int wid = tid >> 5;
    const int lane = tid & 31;
    const int bm = blockIdx.y * 128;
    const int bn = blockIdx.x * 128;

    const uint32_t sbase = smem_u32(smem);
    const uint32_t sA0 = sbase;
    const uint32_t sB0 = sbase + 2 * TILE_BYTES;

    const int lr0 = tid >> 2;
    const int lcb = (tid & 3) * 16;
    const int lce = (tid & 3) * 8;

    const __nv_bfloat16* Abase = A + (size_t)(bm + lr0) * Kp + lce;
    const __nv_bfloat16* Bbase = B + (size_t)(bn + lr0) * Kp + lce;

    const int wm = wid & 3;
    const int wn = wid >> 2;
    const uint32_t lmr = lane & 15;
    const uint32_t lmc = (lane >> 4) * 16;

    float acc[2][8][4];
#pragma unroll
    for (int mt = 0; mt < 2; mt++)
#pragma unroll
        for (int nt = 0; nt < 8; nt++)
#pragma unroll
            for (int q = 0; q < 4; q++) acc[mt][nt][q] = 0.f;

    const int iters = Kp / BKQ;

    {
        uint32_t dA = sA0 + lr0 * ROWB + lcb;
        uint32_t dB = sB0 + lr0 * ROWB + lcb;
        cp_async16(dA, Abase);
        cp_async16(dA + 64 * ROWB, Abase + (size_t)64 * Kp);
        cp_async16(dB, Bbase);
        cp_async16(dB + 64 * ROWB, Bbase + (size_t)64 * Kp);
        cp_commit();
    }

    for (int i = 0; i < iters; i++) {
        const int buf = i & 1;
        if (i + 1 < iters) {
            const int nb = buf ^ 1;
            const int k0 = (i + 1) * BKQ;
            uint32_t dA = sA0 + nb * TILE_BYTES + lr0 * ROWB + lcb;
            uint32_t dB = sB0 + nb * TILE_BYTES + lr0 * ROWB + lcb;
            cp_async16(dA, Abase + k0);
            cp_async16(dA + 64 * ROWB, Abase + (size_t)64 * Kp + k0);
            cp_async16(dB, Bbase + k0);
            cp_async16(dB + 64 * ROWB, Bbase + (size_t)64 * Kp + k0);
            cp_commit();
            cp_wait<1>();
        } else {
            cp_wait<0>();
        }
        __syncthreads();

        const uint32_t aTile = sA0 + buf * TILE_BYTES;
        const uint32_t bTile = sB0 + buf * TILE_BYTES;

#pragma unroll
        for (int ks = 0; ks < 2; ks++) {
            uint32_t af[2][4];
#pragma unroll
            for (int mt = 0; mt < 2; mt++) {
                uint32_t addr = aTile + (wm * 32 + mt * 16 + lmr) * ROWB +
                                ks * 32 + lmc;
                ldm_x4(addr, af[mt][0], af[mt][1], af[mt][2], af[mt][3]);
            }
            uint32_t bf[4][4];
#pragma unroll
            for (int bt = 0; bt < 4; bt++) {
                uint32_t addr = bTile + (wn * 64 + bt * 16 + lmr) * ROWB +
                                ks * 32 + lmc;
                ldm_x4(addr, bf[bt][0], bf[bt][1], bf[bt][2], bf[bt][3]);
            }
#pragma unroll
            for (int mt = 0; mt < 2; mt++)
#pragma unroll
                for (int nt = 0; nt < 8; nt++) {
                    uint32_t b0 = bf[nt >> 1][nt & 1];
                    uint32_t b1 = bf[nt >> 1][(nt & 1) + 2];
                    mma_16816(acc[mt][nt], af[mt], b0, b1);
                }
        }
        __syncthreads();
    }

    const int cr = lane >> 2;
    const int cc = (lane & 3) * 2;
#pragma unroll
    for (int mt = 0; mt < 2; mt++) {
        int r0 = bm + wm * 32 + mt * 16 + cr;
#pragma unroll
        for (int nt = 0; nt < 8; nt++) {
            int col = bn + wn * 64 + nt * 8 + cc;
            float2 v0 = make_float2(acc[mt][nt][0], acc[mt][nt][1]);
            float2 v1 = make_float2(acc[mt][nt][2], acc[mt][nt][3]);
            *(float2*)(C + (size_t)r0 * N + col) = v0;
            *(float2*)(C + (size_t)(r0 + 8) * N + col) = v1;
        }
    }
}

// ---------------------------------------------------------------------------
// HMMA flash attention. Block = (qt, h, b), 128 threads (4 warps).
// 64 q-rows/CTA, warp w owns rows [16w,16w+16). Split-precision:
//   S  = Qh.Kh + Ql.Kh + Qh.Kl   (hi = bf16 truncation, lo = residual)
//   PV = Ph.Vh + Pl.Vh + Ph.Vl   (P frags built from S accum registers)
// logits = (S + bias)*8, causal, online softmax per-warp in registers.
// Output written directly as hi/lo-split bf16 ys ([hi|lo|hi] along K').
// ---------------------------------------------------------------------------
#define AROW 144   // smem row stride bytes (64 bf16 = 128B + 16 pad)

__global__ __launch_bounds__(128) void attn_mma(const float* __restrict__ qkv,
                                                const float* __restrict__ pbias,
                                                __nv_bfloat16* __restrict__ ys) {
    __shared__ __align__(16) char sm_raw[4 * 64 * AROW]; // 36864 B
    const uint32_t sb = smem_u32(sm_raw);
    const uint32_t sKh = sb;
    const uint32_t sKl = sb + 64 * AROW;
    const uint32_t sVh = sb + 2 * 64 * AROW;   // also Q hi staging
    const uint32_t sVl = sb + 3 * 64 * AROW;   // also Q lo staging

    const int tid = threadIdx.x;
    const int wid = tid >> 5;
    const int lane = tid & 31;
    const int qt = blockIdx.x;
    const int h = blockIdx.y;
    const int b = blockIdx.z;
    const int t0 = qt * 64;
    const int cr = lane >> 2;
    const int cc = (lane & 3) * 2;
    const uint32_t lmr = lane & 15;
    const uint32_t lmc = (lane >> 4) * 16;

    // ---- stage Q (hi/lo) into sVh/sVl ----
#pragma unroll
    for (int p = 0; p < 8; p++) {
        int linear = p * 128 + tid;
        int srow = linear >> 4;
        int col = (linear & 15) * 4;
        const float* gq = qkv + ((size_t)(b * T_SZ + t0 + srow)) * QKV_N + h * D_SZ + col;
        float4 v = *(const float4*)gq;
        uint32_t h01 = prmt_hi(v.x, v.y);
        uint32_t h23 = prmt_hi(v.z, v.w);
        uint32_t l01 = cvt_bf2(v.x - ftrunc_bf(v.x), v.y - ftrunc_bf(v.y));
        uint32_t l23 = cvt_bf2(v.z - ftrunc_bf(v.z), v.w - ftrunc_bf(v.w));
        uint32_t off = srow * AROW + col * 2;
        *(uint32_t*)(sm_raw + (sVh - sb) + off) = h01;
        *(uint32_t*)(sm_raw + (sVh - sb) + off + 4) = h23;
        *(uint32_t*)(sm_raw + (sVl - sb) + off) = l01;
        *(uint32_t*)(sm_raw + (sVl - sb) + off + 4) = l23;
    }
    __syncthreads();

    // ---- preload Q fragments (hi and lo) ----
    uint32_t afh[4][4], afl[4][4];
#pragma unroll
    for (int ks = 0; ks < 4; ks++) {
        uint32_t addr = sVh + (wid * 16 + lmr) * AROW + ks * 32 + lmc;
        ldm_x4(addr, afh[ks][0], afh[ks][1], afh[ks][2], afh[ks][3]);
        addr = sVl + (wid * 16 + lmr) * AROW + ks * 32 + lmc;
        ldm_x4(addr, afl[ks][0], afl[ks][1], afl[ks][2], afl[ks][3]);
    }

    float oacc[8][4];
#pragma unroll
    for (int nt = 0; nt < 8; nt++)
#pragma unroll
        for (int q = 0; q < 4; q++) oacc[nt][q] = 0.f;
    float mA = -1e30f, mB = -1e30f, lA = 0.f, lB = 0.f;

    const int rowA = t0 + wid * 16 + cr;      // absolute t for c0,c1
    const int rowB = rowA + 8;                // absolute t for c2,c3
    const float* biasA = pbias + ((size_t)h * T_SZ + rowA) * T_SZ;
    const float* biasB = pbias + ((size_t)h * T_SZ + rowB) * T_SZ;

    for (int kt = 0; kt <= qt; kt++) {
        const int s0 = kt * 64;
        __syncthreads();   // prior iteration's ldmatrix reads done

        // ---- load K and V tiles (hi/lo) ----
#pragma unroll
        for (int p = 0; p < 8; p++) {
            int linear = p * 128 + tid;
            int srow = linear >> 4;
            int col = (linear & 15) * 4;
            size_t base = ((size_t)(b * T_SZ + s0 + srow)) * QKV_N + h * D_SZ + col;
            uint32_t off = srow * AROW + col * 2;
            float4 kv = *(const float4*)(qkv + C_SZ + base);
            *(uint32_t*)(sm_raw + (sKh - sb) + off)     = prmt_hi(kv.x, kv.y);
            *(uint32_t*)(sm_raw + (sKh - sb) + off + 4) = prmt_hi(kv.z, kv.w);
            *(uint32_t*)(sm_raw + (sKl - sb) + off) =
                cvt_bf2(kv.x - ftrunc_bf(kv.x), kv.y - ftrunc_bf(kv.y));
            *(uint32_t*)(sm_raw + (sKl - sb) + off + 4) =
                cvt_bf2(kv.z - ftrunc_bf(kv.z), kv.w - ftrunc_bf(kv.w));
            float4 vv = *(const float4*)(qkv + 2 * C_SZ + base);
            *(uint32_t*)(sm_raw + (sVh - sb) + off)     = prmt_hi(vv.x, vv.y);
            *(uint32_t*)(sm_raw + (sVh - sb) + off + 4) = prmt_hi(vv.z, vv.w);
            *(uint32_t*)(sm_raw + (sVl - sb) + off) =
                cvt_bf2(vv.x - ftrunc_bf(vv.x), vv.y - ftrunc_bf(vv.y));
            *(uint32_t*)(sm_raw + (sVl - sb) + off + 4) =
                cvt_bf2(vv.z - ftrunc_bf(vv.z), vv.w - ftrunc_bf(vv.w));
        }
        __syncthreads();

        // ---- S = Q.K^T (3 split passes) ----
        float sacc[8][4];
#pragma unroll
        for (int nt = 0; nt < 8; nt++)
#pragma unroll
            for (int q = 0; q < 4; q++) sacc[nt][q] = 0.f;

#pragma unroll
        for (int ks = 0; ks < 4; ks++) {
#pragma unroll
            for (int g = 0; g < 4; g++) {
                uint32_t b0, b1, b2, b3;
                ldm_x4(sKh + (g * 16 + lmr) * AROW + ks * 32 + lmc, b0, b1, b2, b3);
                mma_16816(sacc[2 * g],     afh[ks], b0, b2);
                mma_16816(sacc[2 * g + 1], afh[ks], b1, b3);
                mma_16816(sacc[2 * g],     afl[ks], b0, b2);
                mma_16816(sacc[2 * g + 1], afl[ks], b1, b3);
                ldm_x4(sKl + (g * 16 + lmr) * AROW + ks * 32 + lmc, b0, b1, b2, b3);
                mma_16816(sacc[2 * g],     afh[ks], b0, b2);
                mma_16816(sacc[2 * g + 1], afh[ks], b1, b3);
            }
        }

        // ---- bias, scale, causal mask ----
#pragma unroll
        for (int nt = 0; nt < 8; nt++) {
            int col = s0 + nt * 8 + cc;
            float2 bA = *(const float2*)(biasA + col);
            float2 bB = *(const float2*)(biasB + col);
            sacc[nt][0] = (col     > rowA) ? -1e30f : (sacc[nt][0] + bA.x) * 8.0f;
            sacc[nt][1] = (col + 1 > rowA) ? -1e30f : (sacc[nt][1] + bA.y) * 8.0f;
            sacc[nt][2] = (col     > rowB) ? -1e30f : (sacc[nt][2] + bB.x) * 8.0f;
            sacc[nt][3] = (col + 1 > rowB) ? -1e30f : (sacc[nt][3] + bB.y) * 8.0f;
        }

        // ---- online softmax (register-local per warp) ----
        float mxA = -1e30f, mxB = -1e30f;
#pragma unroll
        for (int nt = 0; nt < 8; nt++) {
            mxA = fmaxf(mxA, fmaxf(sacc[nt][0], sacc[nt][1]));
            mxB = fmaxf(mxB, fmaxf(sacc[nt][2], sacc[nt][3]));
        }
        mxA = qmax(mxA); mxB = qmax(mxB);
        float mnA = fmaxf(mA, mxA), mnB = fmaxf(mB, mxB);
        float aA = __expf(mA - mnA), aB = __expf(mB - mnB);
        mA = mnA; mB = mnB;
        float sA = 0.f, sB = 0.f;
#pragma unroll
        for (int nt = 0; nt < 8; nt++) {
            float p0 = __expf(sacc[nt][0] - mA);
            float p1 = __expf(sacc[nt][1] - mA);
            float p2 = __expf(sacc[nt][2] - mB);
            float p3 = __expf(sacc[nt][3] - mB);
            sacc[nt][0] = p0; sacc[nt][1] = p1; sacc[nt][2] = p2; sacc[nt][3] = p3;
            sA += p0 + p1; sB += p2 + p3;
            oacc[nt][0] *= aA; oacc[nt][1] *= aA;
            oacc[nt][2] *= aB; oacc[nt][3] *= aB;
        }
        lA = lA * aA + qsum(sA);
        lB = lB * aB + qsum(sB);

        // ---- PV: oacc += P.V (3 split passes) ----
#pragma unroll
        for (int ks = 0; ks < 4; ks++) {
            uint32_t pah[4], pal[4];
            {
                float p0 = sacc[2 * ks][0], p1 = sacc[2 * ks][1];
                float p2 = sacc[2 * ks][2], p3 = sacc[2 * ks][3];
                float q0 = sacc[2 * ks + 1][0], q1 = sacc[2 * ks + 1][1];
                float q2 = sacc[2 * ks + 1][2], q3 = sacc[2 * ks + 1][3];
                pah[0] = prmt_hi(p0, p1);
                pah[1] = prmt_hi(p2, p3);
                pah[2] = prmt_hi(q0, q1);
                pah[3] = prmt_hi(q2, q3);
                pal[0] = cvt_bf2(p0 - ftrunc_bf(p0), p1 - ftrunc_bf(p1));
                pal[1] = cvt_bf2(p2 - ftrunc_bf(p2), p3 - ftrunc_bf(p3));
                pal[2] = cvt_bf2(q0 - ftrunc_bf(q0), q1 - ftrunc_bf(q1));
                pal[3] = cvt_bf2(q2 - ftrunc_bf(q2), q3 - ftrunc_bf(q3));
            }
#pragma unroll
            for (int g = 0; g < 4; g++) {
                uint32_t r0, r1, r2, r3;
                ldm_x4_t(sVh + (ks * 16 + lmr) * AROW + g * 32 + lmc, r0, r1, r2, r3);
                mma_16816(oacc[2 * g],     pah, r0, r1);
                mma_16816(oacc[2 * g + 1], pah, r2, r3);
                mma_16816(oacc[2 * g],     pal, r0, r1);
                mma_16816(oacc[2 * g + 1], pal, r2, r3);
                ldm_x4_t(sVl + (ks * 16 + lmr) * AROW + g * 32 + lmc, r0, r1, r2, r3);
                mma_16816(oacc[2 * g],     pah, r0, r1);
                mma_16816(oacc[2 * g + 1], pah, r2, r3);
            }
        }
    }

    // ---- epilogue: y -> split bf16 ys ([hi|lo|hi]) ----
    float invA = 1.0f / lA, invB = 1.0f / lB;
    const size_t growA = (size_t)(b * T_SZ) + rowA;
    const size_t growB = (size_t)(b * T_SZ) + rowB;
#pragma unroll
    for (int nt = 0; nt < 8; nt++) {
        int gcol = h * D_SZ + nt * 8 + cc;
        float v0 = oacc[nt][0] * invA, v1 = oacc[nt][1] * invA;
        float v2 = oacc[nt][2] * invB, v3 = oacc[nt][3] * invB;
        uint32_t hA = prmt_hi(v0, v1);
        uint32_t lAo = cvt_bf2(v0 - ftrunc_bf(v0), v1 - ftrunc_bf(v1));
        uint32_t hB = prmt_hi(v2, v3);
        uint32_t lBo = cvt_bf2(v2 - ftrunc_bf(v2), v3 - ftrunc_bf(v3));
        uint32_t* oA = (uint32_t*)(ys + growA * KP + gcol);
        uint32_t* oB = (uint32_t*)(ys + growB * KP + gcol);
        oA[0] = hA; oA[512] = lAo; oA[1024] = hA;
        oB[0] = hB; oB[512] = lBo; oB[1024] = hB;
    }
}

// ---------------------------------------------------------------------------
extern "C" void kernel_launch(void* const* d_in, const int* in_sizes, int n_in,
                              void* d_out, int out_size) {
    const float* x      = (const float*)d_in[0];
    const float* pbias  = (const float*)d_in[1];
    const float* W_attn = (const float*)d_in[2];
    const float* W_proj = (const float*)d_in[3];
    float* out = (float*)d_out;

    float* qkv = nullptr;
    __nv_bfloat16 *xs = nullptr, *was = nullptr, *wps = nullptr, *ys = nullptr;
    cudaGetSymbolAddress((void**)&qkv, g_qkv);
    cudaGetSymbolAddress((void**)&xs, g_xs);
    cudaGetSymbolAddress((void**)&was, g_was);
    cudaGetSymbolAddress((void**)&wps, g_wps);
    cudaGetSymbolAddress((void**)&ys, g_ys);

    // Split inputs to bf16 hi/lo concatenated along K
    split_bf16<<<(M_SZ * 512 + 255) / 256, 256>>>(x, xs, M_SZ, 0);
    split_bf16<<<(QKV_N * 512 + 255) / 256, 256>>>(W_attn, was, QKV_N, 1);
    split_bf16<<<(C_SZ * 512 + 255) / 256, 256>>>(W_proj, wps, C_SZ, 1);

    // 1) qkv = x @ W_attn^T via HMMA (K' = 3072)
    {
        dim3 grid(QKV_N / 128, M_SZ / 128);
        gemm_mma<<<grid, 256>>>(xs, was, qkv, M_SZ, QKV_N, KP);
    }
    // 2) fused causal attention (HMMA, writes split ys directly)
    {
        dim3 grid(T_SZ / 64, H_SZ, B_SZ);
        attn_mma<<<grid, 128>>>(qkv, pbias, ys);
    }
    // 3) out = y @ W_proj^T via HMMA
    {
        dim3 grid(C_SZ / 128, M_SZ / 128);
        gemm_mma<<<grid, 256>>>(ys, wps, out, M_SZ, C_SZ, KP);
    }
}